// round 1
// baseline (speedup 1.0000x reference)
#include <cuda_runtime.h>

// Problem constants
#define BB 16
#define MM 4096
#define TT 4
#define DD 256
#define VV 40000
#define CONV 512
#define BD (BB*DD)          // 4096
#define BM (BB*MM)          // 65536
#define NCHUNK 32
#define CHUNK (MM/NCHUNK)   // 128
#define EMB_SZ ((size_t)BB*MM*DD)  // 16777216 elements (64MB)

// ---------------- device scratch (allocation-free) ----------------
__device__ float g_emb[3*16777216];      // emb[0..2], 192MB; emb[3] lives in d_out
__device__ float g_logit[BM];
__device__ float g_prob[BM];
__device__ float g_ulist[2*4*BD];        // double-buffered u[0..3] per layer
__device__ float g_q[BD];                // q after FW relu
__device__ float g_uf[BD];               // pointer-loop state
__device__ float g_part[NCHUNK*BD];      // deterministic partial sums for o_k

// ---------------- kernels ----------------

// emb[h][b,m,:] = sum_t C[h][story[b,m,t],:]  (+ history in the conv window)
__global__ void k_embed(const int* __restrict__ story, const int* __restrict__ kb_len,
                        const int* __restrict__ conv_len, const float* __restrict__ hist,
                        const float* __restrict__ C_emb, float* __restrict__ emb3){
    int h = blockIdx.z, b = blockIdx.y;
    int m0 = blockIdx.x * CHUNK;
    int d = threadIdx.x;
    const float* table = C_emb + (size_t)h*VV*DD;
    int start = kb_len[b], clen = conv_len[b];
    float* dst = (h < 3) ? g_emb + (size_t)h*EMB_SZ + (size_t)b*MM*DD
                         : emb3  + (size_t)b*MM*DD;
    const float* hb = hist + (size_t)b*CONV*DD;
    for(int mi = 0; mi < CHUNK; ++mi){
        int m = m0 + mi;
        int4 tok = *reinterpret_cast<const int4*>(story + (size_t)(b*MM + m)*TT);
        float acc = table[(size_t)tok.x*DD + d] + table[(size_t)tok.y*DD + d]
                  + table[(size_t)tok.z*DD + d] + table[(size_t)tok.w*DD + d];
        int r = m - start;
        if (r >= 0 && r < clen) acc += hb[(size_t)r*DD + d];
        dst[(size_t)m*DD + d] = acc;
    }
}

// init u0 = query, uf = query_vector
__global__ void k_init(const float* __restrict__ query, const float* __restrict__ qv){
    int b = blockIdx.x, d = threadIdx.x;
    g_ulist[0*BD + b*DD + d] = query[b*DD + d];
    g_uf[b*DD + d] = qv[b*DD + d];
}

// logit[b,m] = emb[eh][b,m,:] . u[b,:]   (optionally * gp[b,m])
__global__ void k_logit(int eh, const float* __restrict__ emb3, int u_is_uf, int cur, int uh,
                        int use_gp, const float* __restrict__ gp, float* __restrict__ out_ext){
    int b = blockIdx.y;
    const float* emb = (eh < 3) ? g_emb + (size_t)eh*EMB_SZ : emb3;
    const float* u = u_is_uf ? (g_uf + b*DD) : (g_ulist + (size_t)(cur*4 + uh)*BD + b*DD);
    float* out = out_ext ? out_ext : g_logit;
    __shared__ float4 su[DD/4];
    if (threadIdx.x < DD/4) su[threadIdx.x] = reinterpret_cast<const float4*>(u)[threadIdx.x];
    __syncthreads();
    int warp = threadIdx.x >> 5, lane = threadIdx.x & 31;
    int mbase = blockIdx.x*64 + warp*8;
    for(int i = 0; i < 8; ++i){
        int m = mbase + i;
        const float4* row = reinterpret_cast<const float4*>(emb + ((size_t)b*MM + m)*DD);
        float4 v0 = row[lane], v1 = row[lane + 32];
        float4 u0 = su[lane], u1 = su[lane + 32];
        float acc = v0.x*u0.x + v0.y*u0.y + v0.z*u0.z + v0.w*u0.w
                  + v1.x*u1.x + v1.y*u1.y + v1.z*u1.z + v1.w*u1.w;
        #pragma unroll
        for(int off = 16; off; off >>= 1) acc += __shfl_down_sync(0xffffffffu, acc, off);
        if (lane == 0){
            if (use_gp) acc *= gp[b*MM + m];
            out[b*MM + m] = acc;
        }
    }
}

// row softmax over M per batch
__global__ void k_softmax(const float* __restrict__ in_ext, float* __restrict__ out_ext){
    int b = blockIdx.x, t = threadIdx.x;
    const float* in = in_ext ? in_ext : g_logit;
    float* out = out_ext ? out_ext : g_prob;
    __shared__ float sval[MM];
    __shared__ float sred[256];
    float mx = -3.0e38f;
    for(int i = t; i < MM; i += 256){ float v = in[b*MM + i]; sval[i] = v; mx = fmaxf(mx, v); }
    sred[t] = mx; __syncthreads();
    for(int s = 128; s; s >>= 1){ if (t < s) sred[t] = fmaxf(sred[t], sred[t+s]); __syncthreads(); }
    float m = sred[0]; __syncthreads();
    float sum = 0.f;
    for(int i = t; i < MM; i += 256){ float e = expf(sval[i] - m); sval[i] = e; sum += e; }
    sred[t] = sum; __syncthreads();
    for(int s = 128; s; s >>= 1){ if (t < s) sred[t] += sred[t+s]; __syncthreads(); }
    float inv = 1.0f / sred[0];
    for(int i = t; i < MM; i += 256) out[b*MM + i] = sval[i]*inv;
}

// partial o_k: g_part[c][b,d] = sum_{m in chunk c} prob[b,m] (*gp) * emb[eh][b,m,d]
__global__ void k_o(int eh, const float* __restrict__ emb3, int use_gp,
                    const float* __restrict__ gp, const float* __restrict__ prob_ext){
    int b = blockIdx.y, c = blockIdx.x, d = threadIdx.x;
    const float* emb = (eh < 3) ? g_emb + (size_t)eh*EMB_SZ : emb3;
    const float* prob = prob_ext ? prob_ext : g_prob;
    __shared__ float sp[CHUNK];
    int m0 = c*CHUNK;
    if (d < CHUNK){
        float p = prob[b*MM + m0 + d];
        if (use_gp) p *= gp[b*MM + m0 + d];
        sp[d] = p;
    }
    __syncthreads();
    const float* base = emb + ((size_t)b*MM + m0)*DD;
    float acc = 0.f;
    #pragma unroll 4
    for(int mi = 0; mi < CHUNK; ++mi) acc += sp[mi]*base[(size_t)mi*DD + d];
    g_part[c*BD + b*DD + d] = acc;
}

// u[hop+1] = (u[hop] + o)  possibly gated with Tg_w[hop+1], last_u[hop+1]
__global__ void k_update(int hop, int gated, int cur, int prev,
                         const float* __restrict__ Tg_w, const float* __restrict__ Tg_b){
    int b = blockIdx.x, d = threadIdx.x;
    __shared__ float s_un[DD];
    float o = 0.f;
    #pragma unroll
    for(int c = 0; c < NCHUNK; ++c) o += g_part[c*BD + b*DD + d];
    float un = g_ulist[(size_t)(cur*4 + hop)*BD + b*DD + d] + o;
    s_un[d] = un; __syncthreads();
    float out = un;
    if (gated){
        const float* w = Tg_w + (size_t)(hop+1)*DD*DD + (size_t)d*DD;
        float acc = Tg_b[(hop+1)*DD + d];
        #pragma unroll 8
        for(int k = 0; k < DD; ++k) acc += w[k]*s_un[k];
        float g = 1.0f/(1.0f + expf(-acc));
        out = g_ulist[(size_t)(prev*4 + hop + 1)*BD + b*DD + d]*g + un*(1.0f - g);
    }
    g_ulist[(size_t)(cur*4 + hop + 1)*BD + b*DD + d] = out;
}

// layer-start gate on iq (layer > 0): u0 = last_u[0]*g + q*(1-g), g = sigmoid(q @ Tg_w[0].T + b0)
__global__ void k_gate0(int cur, int prev, const float* __restrict__ Tg_w,
                        const float* __restrict__ Tg_b){
    int b = blockIdx.x, d = threadIdx.x;
    __shared__ float sq[DD];
    float q = g_q[b*DD + d]; sq[d] = q; __syncthreads();
    const float* w = Tg_w + (size_t)d*DD;
    float acc = Tg_b[d];
    #pragma unroll 8
    for(int k = 0; k < DD; ++k) acc += w[k]*sq[k];
    float g = 1.0f/(1.0f + expf(-acc));
    g_ulist[(size_t)(cur*4)*BD + b*DD + d] =
        g_ulist[(size_t)(prev*4)*BD + b*DD + d]*g + q*(1.0f - g);
}

// q = relu(u3 @ FW_w.T + FW_b)
__global__ void k_fw(int cur, const float* __restrict__ FW_w, const float* __restrict__ FW_b){
    int b = blockIdx.x, d = threadIdx.x;
    __shared__ float su[DD];
    float u3 = g_ulist[(size_t)(cur*4 + 3)*BD + b*DD + d]; su[d] = u3; __syncthreads();
    const float* w = FW_w + (size_t)d*DD;
    float acc = FW_b[d];
    #pragma unroll 8
    for(int k = 0; k < DD; ++k) acc += w[k]*su[k];
    g_q[b*DD + d] = fmaxf(acc, 0.0f);
}

// uf += reduced partials; optionally also write to d_out
__global__ void k_uf_add(float* __restrict__ out){
    int b = blockIdx.x, d = threadIdx.x;
    float o = 0.f;
    #pragma unroll
    for(int c = 0; c < NCHUNK; ++c) o += g_part[c*BD + b*DD + d];
    float v = g_uf[b*DD + d] + o;
    g_uf[b*DD + d] = v;
    if (out) out[b*DD + d] = v;
}

// ---------------- launcher ----------------
extern "C" void kernel_launch(void* const* d_in, const int* in_sizes, int n_in,
                              void* d_out, int out_size){
    const int*   story = (const int*)  d_in[0];
    const int*   kb    = (const int*)  d_in[1];
    const int*   cl    = (const int*)  d_in[2];
    const float* query = (const float*)d_in[3];
    const float* hist  = (const float*)d_in[4];
    const float* qv    = (const float*)d_in[5];
    const float* gp    = (const float*)d_in[6];
    const float* C     = (const float*)d_in[7];
    const float* Tgw   = (const float*)d_in[8];
    const float* Tgb   = (const float*)d_in[9];
    const float* FWw   = (const float*)d_in[10];
    const float* FWb   = (const float*)d_in[11];

    float* out        = (float*)d_out;
    float* out_psoft  = out;                 // (B, M)
    float* out_logits = out + BM;            // (B, M)
    float* out_uf     = out + 2*BM;          // (B, D)
    float* out_emb3   = out + 2*BM + BD;     // (B, M, D) = m_story[-1]

    // 1) materialize the four layer-invariant embeddings (emb3 straight into d_out)
    k_embed<<<dim3(NCHUNK, BB, 4), DD>>>(story, kb, cl, hist, C, out_emb3);
    k_init<<<BB, DD>>>(query, qv);

    // 2) layer loop (3 layers x 3 hops)
    for(int layer = 0; layer < 3; ++layer){
        int cur = layer & 1, prev = cur ^ 1;
        if (layer > 0) k_gate0<<<BB, DD>>>(cur, prev, Tgw, Tgb);
        for(int hop = 0; hop < 3; ++hop){
            k_logit<<<dim3(MM/64, BB), 256>>>(hop, out_emb3, 0, cur, hop, 0, gp, nullptr);
            k_softmax<<<BB, 256>>>(nullptr, nullptr);
            k_o<<<dim3(NCHUNK, BB), DD>>>(hop + 1, out_emb3, 0, gp, nullptr);
            k_update<<<BB, DD>>>(hop, layer > 0 ? 1 : 0, cur, prev, Tgw, Tgb);
        }
        if (layer < 2) k_fw<<<BB, DD>>>(cur, FWw, FWb);
    }

    // 3) pointer loop (3 hops); final hop writes psoft/logits/uf into d_out
    for(int hop = 0; hop < 3; ++hop){
        float* lo = (hop == 2) ? out_logits : nullptr;
        float* po = (hop == 2) ? out_psoft  : nullptr;
        k_logit<<<dim3(MM/64, BB), 256>>>(hop, out_emb3, 1, 0, 0, 1, gp, lo);
        k_softmax<<<BB, 256>>>(lo, po);
        k_o<<<dim3(NCHUNK, BB), DD>>>(hop + 1, out_emb3, 1, gp, po);
        k_uf_add<<<BB, DD>>>((hop == 2) ? out_uf : nullptr);
    }
}

// round 4
// speedup vs baseline: 1.1998x; 1.1998x over previous
#include <cuda_runtime.h>

// Problem constants
#define BB 16
#define MM 4096
#define TT 4
#define DD 256
#define VV 40000
#define CONV 512
#define BD (BB*DD)          // 4096
#define BM (BB*MM)          // 65536
#define NCHUNK 32
#define CHUNK (MM/NCHUNK)   // 128
#define EMB_SZ ((size_t)BB*MM*DD)  // 16777216 elements (64MB)

// ---------------- device scratch (allocation-free) ----------------
__device__ float g_emb[3*16777216];      // emb[0..2]; emb[3] lives in d_out
__device__ float g_logit[BM];
__device__ float g_prob[BM];
__device__ float g_ulist[2*4*BD];        // double-buffered u[0..3] per layer
__device__ float g_q[BD];
__device__ float g_uf[BD];
__device__ float g_part[NCHUNK*BD];      // deterministic partial sums for o_k

// ---------------- kernels ----------------

// emb[h][b,m,:] = sum_t C[h][story[b,m,t],:] (+ history in conv window)
// One launch per hop-table so its 40MB table stays L2-resident.
// NOTE: dst resolved IN DEVICE CODE (never take &__device__ symbol on host).
__global__ void __launch_bounds__(256) k_embed(
        int h, const int* __restrict__ story, const int* __restrict__ kb_len,
        const int* __restrict__ conv_len, const float* __restrict__ hist,
        const float* __restrict__ table, float* __restrict__ emb3){
    int b = blockIdx.y;
    int m0 = blockIdx.x * CHUNK;
    int mg = threadIdx.x >> 6;        // 0..3 : row within group of 4
    int d4 = threadIdx.x & 63;        // float4 lane
    int start = kb_len[b], clen = conv_len[b];
    float* dst = ((h < 3) ? (g_emb + (size_t)h*EMB_SZ) : emb3) + (size_t)b*MM*DD;
    const float4* hb = reinterpret_cast<const float4*>(hist + (size_t)b*CONV*DD);
    const float4* t4 = reinterpret_cast<const float4*>(table);
    for(int mi = 0; mi < CHUNK; mi += 4){
        int m = m0 + mi + mg;
        int4 tok = *reinterpret_cast<const int4*>(story + (size_t)(b*MM + m)*TT);
        float4 a = t4[(size_t)tok.x*64 + d4];
        float4 c = t4[(size_t)tok.y*64 + d4];
        float4 e = t4[(size_t)tok.z*64 + d4];
        float4 f = t4[(size_t)tok.w*64 + d4];
        float4 acc;
        acc.x = a.x + c.x + e.x + f.x;
        acc.y = a.y + c.y + e.y + f.y;
        acc.z = a.z + c.z + e.z + f.z;
        acc.w = a.w + c.w + e.w + f.w;
        int r = m - start;
        if (r >= 0 && r < clen){
            float4 hv = hb[(size_t)r*64 + d4];
            acc.x += hv.x; acc.y += hv.y; acc.z += hv.z; acc.w += hv.w;
        }
        reinterpret_cast<float4*>(dst + (size_t)m*DD)[d4] = acc;
    }
}

// init u0 = query, uf = query_vector
__global__ void k_init(const float* __restrict__ query, const float* __restrict__ qv){
    int b = blockIdx.x, d = threadIdx.x;
    g_ulist[0*BD + b*DD + d] = query[b*DD + d];
    g_uf[b*DD + d] = qv[b*DD + d];
}

// logit[b,m] = emb[eh][b,m,:] . u[b,:]   (optionally * gp[b,m])   [R1-proven]
__global__ void k_logit(int eh, const float* __restrict__ emb3, int u_is_uf, int cur, int uh,
                        int use_gp, const float* __restrict__ gp, float* __restrict__ out_ext){
    int b = blockIdx.y;
    const float* emb = (eh < 3) ? g_emb + (size_t)eh*EMB_SZ : emb3;
    const float* u = u_is_uf ? (g_uf + b*DD) : (g_ulist + (size_t)(cur*4 + uh)*BD + b*DD);
    float* out = out_ext ? out_ext : g_logit;
    __shared__ float4 su[DD/4];
    if (threadIdx.x < DD/4) su[threadIdx.x] = reinterpret_cast<const float4*>(u)[threadIdx.x];
    __syncthreads();
    int warp = threadIdx.x >> 5, lane = threadIdx.x & 31;
    int mbase = blockIdx.x*64 + warp*8;
    for(int i = 0; i < 8; ++i){
        int m = mbase + i;
        const float4* row = reinterpret_cast<const float4*>(emb + ((size_t)b*MM + m)*DD);
        float4 v0 = row[lane], v1 = row[lane + 32];
        float4 u0 = su[lane], u1 = su[lane + 32];
        float acc = v0.x*u0.x + v0.y*u0.y + v0.z*u0.z + v0.w*u0.w
                  + v1.x*u1.x + v1.y*u1.y + v1.z*u1.z + v1.w*u1.w;
        #pragma unroll
        for(int off = 16; off; off >>= 1) acc += __shfl_down_sync(0xffffffffu, acc, off);
        if (lane == 0){
            if (use_gp) acc *= gp[b*MM + m];
            out[b*MM + m] = acc;
        }
    }
}

// row softmax over M per batch: 1024 threads, 4 register-cached values/thread
__global__ void __launch_bounds__(1024) k_softmax(const float* __restrict__ in_ext,
                                                  float* __restrict__ out_ext){
    int b = blockIdx.x, t = threadIdx.x;
    const float* in = in_ext ? in_ext : g_logit;
    float* out = out_ext ? out_ext : g_prob;
    __shared__ float sred[1024];
    float v[4];
    float mx = -3.0e38f;
    #pragma unroll
    for(int i = 0; i < 4; ++i){ v[i] = in[b*MM + t + i*1024]; mx = fmaxf(mx, v[i]); }
    sred[t] = mx; __syncthreads();
    for(int s = 512; s; s >>= 1){ if (t < s) sred[t] = fmaxf(sred[t], sred[t+s]); __syncthreads(); }
    float m = sred[0]; __syncthreads();
    float sum = 0.f;
    #pragma unroll
    for(int i = 0; i < 4; ++i){ v[i] = expf(v[i] - m); sum += v[i]; }
    sred[t] = sum; __syncthreads();
    for(int s = 512; s; s >>= 1){ if (t < s) sred[t] += sred[t+s]; __syncthreads(); }
    float inv = 1.0f / sred[0];
    #pragma unroll
    for(int i = 0; i < 4; ++i) out[b*MM + t + i*1024] = v[i]*inv;
}

// partial o_k: g_part[c][b,:] = sum_{m in chunk c} prob[b,m] (*gp) * emb[eh][b,m,:]
__global__ void __launch_bounds__(256) k_o(
        int eh, const float* __restrict__ emb3, int use_gp,
        const float* __restrict__ gp, const float* __restrict__ prob_ext){
    int b = blockIdx.y, c = blockIdx.x;
    const float* emb = (eh < 3) ? g_emb + (size_t)eh*EMB_SZ : emb3;
    const float* prob = prob_ext ? prob_ext : g_prob;
    __shared__ float sp[CHUNK];
    __shared__ float4 sacc[4][64];
    int t = threadIdx.x, rg = t >> 6, d4 = t & 63;
    int m0 = c*CHUNK;
    if (t < CHUNK){
        float p = prob[b*MM + m0 + t];
        if (use_gp) p *= gp[b*MM + m0 + t];
        sp[t] = p;
    }
    __syncthreads();
    const float4* base = reinterpret_cast<const float4*>(emb + ((size_t)b*MM + m0)*DD);
    float4 acc = make_float4(0.f, 0.f, 0.f, 0.f);
    #pragma unroll 4
    for(int mi = rg; mi < CHUNK; mi += 4){
        float p = sp[mi];
        float4 v = base[(size_t)mi*64 + d4];
        acc.x += p*v.x; acc.y += p*v.y; acc.z += p*v.z; acc.w += p*v.w;
    }
    sacc[rg][d4] = acc;
    __syncthreads();
    if (t < 64){
        float4 a0 = sacc[0][t], a1 = sacc[1][t], a2 = sacc[2][t], a3 = sacc[3][t];
        float4 r;
        r.x = a0.x + a1.x + a2.x + a3.x;
        r.y = a0.y + a1.y + a2.y + a3.y;
        r.z = a0.z + a1.z + a2.z + a3.z;
        r.w = a0.w + a1.w + a2.w + a3.w;
        reinterpret_cast<float4*>(g_part + (size_t)c*BD + b*DD)[t] = r;
    }
}

// u[hop+1] = (u[hop] + o), possibly gated   [R1-proven]
__global__ void k_update(int hop, int gated, int cur, int prev,
                         const float* __restrict__ Tg_w, const float* __restrict__ Tg_b){
    int b = blockIdx.x, d = threadIdx.x;
    __shared__ float s_un[DD];
    float o = 0.f;
    #pragma unroll
    for(int c = 0; c < NCHUNK; ++c) o += g_part[c*BD + b*DD + d];
    float un = g_ulist[(size_t)(cur*4 + hop)*BD + b*DD + d] + o;
    s_un[d] = un; __syncthreads();
    float out = un;
    if (gated){
        const float* w = Tg_w + (size_t)(hop+1)*DD*DD + (size_t)d*DD;
        float acc = Tg_b[(hop+1)*DD + d];
        #pragma unroll 8
        for(int k = 0; k < DD; ++k) acc += w[k]*s_un[k];
        float g = 1.0f/(1.0f + expf(-acc));
        out = g_ulist[(size_t)(prev*4 + hop + 1)*BD + b*DD + d]*g + un*(1.0f - g);
    }
    g_ulist[(size_t)(cur*4 + hop + 1)*BD + b*DD + d] = out;
}

// layer-start gate (layer > 0)   [R1-proven]
__global__ void k_gate0(int cur, int prev, const float* __restrict__ Tg_w,
                        const float* __restrict__ Tg_b){
    int b = blockIdx.x, d = threadIdx.x;
    __shared__ float sq[DD];
    float q = g_q[b*DD + d]; sq[d] = q; __syncthreads();
    const float* w = Tg_w + (size_t)d*DD;
    float acc = Tg_b[d];
    #pragma unroll 8
    for(int k = 0; k < DD; ++k) acc += w[k]*sq[k];
    float g = 1.0f/(1.0f + expf(-acc));
    g_ulist[(size_t)(cur*4)*BD + b*DD + d] =
        g_ulist[(size_t)(prev*4)*BD + b*DD + d]*g + q*(1.0f - g);
}

// q = relu(u3 @ FW_w.T + FW_b)   [R1-proven]
__global__ void k_fw(int cur, const float* __restrict__ FW_w, const float* __restrict__ FW_b){
    int b = blockIdx.x, d = threadIdx.x;
    __shared__ float su[DD];
    float u3 = g_ulist[(size_t)(cur*4 + 3)*BD + b*DD + d]; su[d] = u3; __syncthreads();
    const float* w = FW_w + (size_t)d*DD;
    float acc = FW_b[d];
    #pragma unroll 8
    for(int k = 0; k < DD; ++k) acc += w[k]*su[k];
    g_q[b*DD + d] = fmaxf(acc, 0.0f);
}

// uf += reduced partials; optionally also write to d_out   [R1-proven]
__global__ void k_uf_add(float* __restrict__ out){
    int b = blockIdx.x, d = threadIdx.x;
    float o = 0.f;
    #pragma unroll
    for(int c = 0; c < NCHUNK; ++c) o += g_part[c*BD + b*DD + d];
    float v = g_uf[b*DD + d] + o;
    g_uf[b*DD + d] = v;
    if (out) out[b*DD + d] = v;
}

// ---------------- launcher ----------------
extern "C" void kernel_launch(void* const* d_in, const int* in_sizes, int n_in,
                              void* d_out, int out_size){
    const int*   story = (const int*)  d_in[0];
    const int*   kb    = (const int*)  d_in[1];
    const int*   cl    = (const int*)  d_in[2];
    const float* query = (const float*)d_in[3];
    const float* hist  = (const float*)d_in[4];
    const float* qv    = (const float*)d_in[5];
    const float* gp    = (const float*)d_in[6];
    const float* C     = (const float*)d_in[7];
    const float* Tgw   = (const float*)d_in[8];
    const float* Tgb   = (const float*)d_in[9];
    const float* FWw   = (const float*)d_in[10];
    const float* FWb   = (const float*)d_in[11];

    float* out        = (float*)d_out;
    float* out_psoft  = out;                 // (B, M)
    float* out_logits = out + BM;            // (B, M)
    float* out_uf     = out + 2*BM;          // (B, D)
    float* out_emb3   = out + 2*BM + BD;     // (B, M, D) = m_story[-1]

    // 1) embeddings: one launch per hop-table so each 40MB table stays L2-hot.
    //    C is a real device pointer (host arithmetic OK); g_emb is resolved in-kernel.
    for(int h = 0; h < 4; ++h)
        k_embed<<<dim3(NCHUNK, BB), 256>>>(h, story, kb, cl, hist,
                                           C + (size_t)h*VV*DD, out_emb3);
    k_init<<<BB, DD>>>(query, qv);

    // 2) layer loop (3 layers x 3 hops)
    for(int layer = 0; layer < 3; ++layer){
        int cur = layer & 1, prev = cur ^ 1;
        if (layer > 0) k_gate0<<<BB, DD>>>(cur, prev, Tgw, Tgb);
        for(int hop = 0; hop < 3; ++hop){
            k_logit<<<dim3(MM/64, BB), 256>>>(hop, out_emb3, 0, cur, hop, 0, gp, nullptr);
            k_softmax<<<BB, 1024>>>(nullptr, nullptr);
            k_o<<<dim3(NCHUNK, BB), 256>>>(hop + 1, out_emb3, 0, gp, nullptr);
            k_update<<<BB, DD>>>(hop, layer > 0 ? 1 : 0, cur, prev, Tgw, Tgb);
        }
        if (layer < 2) k_fw<<<BB, DD>>>(cur, FWw, FWb);
    }

    // 3) pointer loop; final hop writes psoft/logits/uf into d_out
    for(int hop = 0; hop < 3; ++hop){
        float* lo = (hop == 2) ? out_logits : nullptr;
        float* po = (hop == 2) ? out_psoft  : nullptr;
        k_logit<<<dim3(MM/64, BB), 256>>>(hop, out_emb3, 1, 0, 0, 1, gp, lo);
        k_softmax<<<BB, 1024>>>(lo, po);
        k_o<<<dim3(NCHUNK, BB), 256>>>(hop + 1, out_emb3, 1, gp, po);
        k_uf_add<<<BB, DD>>>((hop == 2) ? out_uf : nullptr);
    }
}

// round 5
// speedup vs baseline: 4.8916x; 4.0770x over previous
#include <cuda_runtime.h>

// Problem constants
#define BB 16
#define MM 4096
#define TT 4
#define DD 256
#define VV 40000
#define CONV 512
#define BD (BB*DD)          // 4096
#define BM (BB*MM)          // 65536
#define ECHUNK 32           // rows per embed block
#define NEB (MM/ECHUNK)     // 128 embed blocks per batch
#define OCHUNK 64           // rows per k_o block
#define NOB (MM/OCHUNK)     // 64 o blocks per batch
#define LBLK 64             // rows per k_logit block
#define NLB (MM/LBLK)       // 64 logit blocks per batch
#define EMB_SZ ((size_t)BB*MM*DD)  // 16777216 elements (64MB)

// ---------------- device scratch (allocation-free) ----------------
__device__ float g_emb[3*16777216];      // emb[0..2]; emb[3] lives in d_out
__device__ float g_logit[BM];
__device__ float g_uf[BD];
__device__ float g_part[NOB*BD];         // deterministic partial sums for o_k
__device__ float g_pmax[BB*NLB];         // per-block softmax partial max
__device__ float g_psum[BB*NLB];         // per-block softmax partial sum(exp)
__device__ float g_smax[BB];             // row max
__device__ float g_sinv[BB];             // 1/row sum

// ---------------- kernels ----------------

// emb[h][b,m,:] = sum_t C[h][story[b,m,t],:] (+ history in conv window)
// dst resolved IN DEVICE CODE (never take &__device__ symbol on host!)
__global__ void __launch_bounds__(256) k_embed(
        int h, const int* __restrict__ story, const int* __restrict__ kb_len,
        const int* __restrict__ conv_len, const float* __restrict__ hist,
        const float* __restrict__ table, float* __restrict__ emb3){
    int b = blockIdx.y;
    int m0 = blockIdx.x * ECHUNK;
    int mg = threadIdx.x >> 6;        // 0..3 : row within group of 4
    int d4 = threadIdx.x & 63;        // float4 lane
    int start = kb_len[b], clen = conv_len[b];
    float* dst = ((h < 3) ? (g_emb + (size_t)h*EMB_SZ) : emb3) + (size_t)b*MM*DD;
    const float4* hb = reinterpret_cast<const float4*>(hist + (size_t)b*CONV*DD);
    const float4* t4 = reinterpret_cast<const float4*>(table);
    #pragma unroll 2
    for(int mi = 0; mi < ECHUNK; mi += 4){
        int m = m0 + mi + mg;
        int4 tok = *reinterpret_cast<const int4*>(story + (size_t)(b*MM + m)*TT);
        float4 a = t4[(size_t)tok.x*64 + d4];
        float4 c = t4[(size_t)tok.y*64 + d4];
        float4 e = t4[(size_t)tok.z*64 + d4];
        float4 f = t4[(size_t)tok.w*64 + d4];
        float4 acc;
        acc.x = a.x + c.x + e.x + f.x;
        acc.y = a.y + c.y + e.y + f.y;
        acc.z = a.z + c.z + e.z + f.z;
        acc.w = a.w + c.w + e.w + f.w;
        int r = m - start;
        if (r >= 0 && r < clen){
            float4 hv = hb[(size_t)r*64 + d4];
            acc.x += hv.x; acc.y += hv.y; acc.z += hv.z; acc.w += hv.w;
        }
        reinterpret_cast<float4*>(dst + (size_t)m*DD)[d4] = acc;
    }
}

// init uf = query_vector
__global__ void k_init(const float* __restrict__ qv){
    g_uf[blockIdx.x*DD + threadIdx.x] = qv[blockIdx.x*DD + threadIdx.x];
}

// logit[b,m] = (emb[eh][b,m,:] * gp[b,m]) . uf[b,:]  + per-block online softmax partials
__global__ void __launch_bounds__(256) k_logit(
        int eh, const float* __restrict__ gp, float* __restrict__ out_ext){
    int b = blockIdx.y;
    const float* emb = g_emb + (size_t)eh*EMB_SZ;   // eh in {0,1,2} only
    const float* u = g_uf + b*DD;
    __shared__ float4 su[DD/4];
    __shared__ float smax[8], ssum[8];
    if (threadIdx.x < DD/4) su[threadIdx.x] = reinterpret_cast<const float4*>(u)[threadIdx.x];
    __syncthreads();
    int warp = threadIdx.x >> 5, lane = threadIdx.x & 31;
    int mbase = blockIdx.x*LBLK + warp*8;
    float lv[8];
    #pragma unroll
    for(int i = 0; i < 8; ++i){
        int m = mbase + i;
        const float4* row = reinterpret_cast<const float4*>(emb + ((size_t)b*MM + m)*DD);
        float4 v0 = row[lane], v1 = row[lane + 32];
        float4 u0 = su[lane], u1 = su[lane + 32];
        float acc = v0.x*u0.x + v0.y*u0.y + v0.z*u0.z + v0.w*u0.w
                  + v1.x*u1.x + v1.y*u1.y + v1.z*u1.z + v1.w*u1.w;
        #pragma unroll
        for(int off = 16; off; off >>= 1) acc += __shfl_down_sync(0xffffffffu, acc, off);
        if (lane == 0) acc *= gp[b*MM + m];      // gp applied BEFORE softmax (reference)
        lv[i] = acc;                              // valid on lane 0 only
    }
    if (lane == 0){
        float mx = lv[0];
        #pragma unroll
        for(int i = 1; i < 8; ++i) mx = fmaxf(mx, lv[i]);
        float sm = 0.f;
        #pragma unroll
        for(int i = 0; i < 8; ++i){
            g_logit[b*MM + mbase + i] = lv[i];
            if (out_ext) out_ext[b*MM + mbase + i] = lv[i];
            sm += expf(lv[i] - mx);
        }
        smax[warp] = mx; ssum[warp] = sm;
    }
    __syncthreads();
    if (threadIdx.x == 0){
        float mx = smax[0];
        #pragma unroll
        for(int w = 1; w < 8; ++w) mx = fmaxf(mx, smax[w]);
        float sm = 0.f;
        #pragma unroll
        for(int w = 0; w < 8; ++w) sm += ssum[w]*expf(smax[w] - mx);
        g_pmax[b*NLB + blockIdx.x] = mx;
        g_psum[b*NLB + blockIdx.x] = sm;
    }
}

// combine per-block softmax partials: one block, warp w handles batch b=w
__global__ void __launch_bounds__(512) k_stats(){
    int w = threadIdx.x >> 5, lane = threadIdx.x & 31;
    float m0 = g_pmax[w*NLB + lane], m1 = g_pmax[w*NLB + lane + 32];
    float s0 = g_psum[w*NLB + lane], s1 = g_psum[w*NLB + lane + 32];
    float mx = fmaxf(m0, m1);
    #pragma unroll
    for(int off = 16; off; off >>= 1) mx = fmaxf(mx, __shfl_xor_sync(0xffffffffu, mx, off));
    float sm = s0*expf(m0 - mx) + s1*expf(m1 - mx);
    #pragma unroll
    for(int off = 16; off; off >>= 1) sm += __shfl_xor_sync(0xffffffffu, sm, off);
    if (lane == 0){ g_smax[w] = mx; g_sinv[w] = 1.0f/sm; }
}

// partial o_k with inline softmax: p = exp(logit-max)*inv; uf-update uses p*gp*embC
__global__ void __launch_bounds__(256) k_o(
        int eh, const float* __restrict__ emb3, const float* __restrict__ gp,
        float* __restrict__ psoft_out){
    int b = blockIdx.y, c = blockIdx.x;
    const float* emb = (eh < 3) ? g_emb + (size_t)eh*EMB_SZ : emb3;
    __shared__ float sp[OCHUNK];
    __shared__ float4 sacc[4][64];
    int t = threadIdx.x, rg = t >> 6, d4 = t & 63;
    int m0 = c*OCHUNK;
    if (t < OCHUNK){
        float mx = g_smax[b], inv = g_sinv[b];
        float p = expf(g_logit[b*MM + m0 + t] - mx)*inv;
        if (psoft_out) psoft_out[b*MM + m0 + t] = p;
        sp[t] = p * gp[b*MM + m0 + t];
    }
    __syncthreads();
    const float4* base = reinterpret_cast<const float4*>(emb + ((size_t)b*MM + m0)*DD);
    float4 acc = make_float4(0.f, 0.f, 0.f, 0.f);
    #pragma unroll 4
    for(int mi = rg; mi < OCHUNK; mi += 4){
        float p = sp[mi];
        float4 v = base[(size_t)mi*64 + d4];
        acc.x += p*v.x; acc.y += p*v.y; acc.z += p*v.z; acc.w += p*v.w;
    }
    sacc[rg][d4] = acc;
    __syncthreads();
    if (t < 64){
        float4 a0 = sacc[0][t], a1 = sacc[1][t], a2 = sacc[2][t], a3 = sacc[3][t];
        float4 r;
        r.x = a0.x + a1.x + a2.x + a3.x;
        r.y = a0.y + a1.y + a2.y + a3.y;
        r.z = a0.z + a1.z + a2.z + a3.z;
        r.w = a0.w + a1.w + a2.w + a3.w;
        reinterpret_cast<float4*>(g_part + (size_t)c*BD + b*DD)[t] = r;
    }
}

// uf += reduced partials; optionally also write to d_out
__global__ void k_uf_add(float* __restrict__ out){
    int b = blockIdx.x, d = threadIdx.x;
    float o = 0.f;
    #pragma unroll
    for(int c = 0; c < NOB; ++c) o += g_part[c*BD + b*DD + d];
    float v = g_uf[b*DD + d] + o;
    g_uf[b*DD + d] = v;
    if (out) out[b*DD + d] = v;
}

// ---------------- launcher ----------------
extern "C" void kernel_launch(void* const* d_in, const int* in_sizes, int n_in,
                              void* d_out, int out_size){
    const int*   story = (const int*)  d_in[0];
    const int*   kb    = (const int*)  d_in[1];
    const int*   cl    = (const int*)  d_in[2];
    const float* hist  = (const float*)d_in[4];
    const float* qv    = (const float*)d_in[5];
    const float* gp    = (const float*)d_in[6];
    const float* C     = (const float*)d_in[7];

    float* out        = (float*)d_out;
    float* out_psoft  = out;                 // (B, M)
    float* out_logits = out + BM;            // (B, M)
    float* out_uf     = out + 2*BM;          // (B, D)
    float* out_emb3   = out + 2*BM + BD;     // (B, M, D) = m_story[-1]

    // NOTE: the reference's 3-layer loop only produces last_u / q, which are
    // never returned. Outputs depend solely on the layer-invariant embeddings
    // and the pointer loop seeded by query_vector — so we compute only those.

    // 1) embeddings: one launch per hop-table so each 40MB table stays L2-hot
    for(int h = 0; h < 4; ++h)
        k_embed<<<dim3(NEB, BB), 256>>>(h, story, kb, cl, hist,
                                        C + (size_t)h*VV*DD, out_emb3);
    k_init<<<BB, DD>>>(qv);

    // 2) pointer loop (3 hops); final hop writes psoft/logits/uf into d_out
    for(int hop = 0; hop < 3; ++hop){
        float* lo = (hop == 2) ? out_logits : nullptr;
        float* po = (hop == 2) ? out_psoft  : nullptr;
        k_logit<<<dim3(NLB, BB), 256>>>(hop, gp, lo);
        k_stats<<<1, 512>>>();
        k_o<<<dim3(NOB, BB), 256>>>(hop + 1, out_emb3, gp, po);
        k_uf_add<<<BB, DD>>>((hop == 2) ? out_uf : nullptr);
    }
}